// round 6
// baseline (speedup 1.0000x reference)
#include <cuda_runtime.h>
#include <mma.h>
using namespace nvcuda;

#define BB 2
#define SS 2048
#define HH 768
#define NH 12
#define DD 64
#define BH (BB*NH)
#define M_PROJ (BB*SS)
#define OUT_ELEMS (BB*SS*HH)
#define ATTN_ELEMS ((size_t)BB*NH*SS*SS)
#define NEGV (-1e32f)

__device__ float g_qh[BB*NH*SS*DD];
__device__ float g_kh[BB*NH*SS*DD];
__device__ float g_vh[BB*NH*SS*DD];
__device__ float g_ctx[BB*SS*HH];
__device__ float g_attn_scratch[BB*NH*SS*SS];

typedef wmma::fragment<wmma::matrix_a, 16, 16, 8, wmma::precision::tf32, wmma::row_major> FragA;
typedef wmma::fragment<wmma::matrix_b, 16, 16, 8, wmma::precision::tf32, wmma::col_major> FragBc;
typedef wmma::fragment<wmma::matrix_b, 16, 16, 8, wmma::precision::tf32, wmma::row_major> FragBr;
typedef wmma::fragment<wmma::accumulator, 16, 16, 8, float> FragC;

#define LDS 36           // 32-k slab + 4 pad
#define SLABK 32
#define NSLAB (HH/SLABK) // 24
#define LDP 68           // 64 + 4
#define LDQ 132          // 128 + 4

#define CVT4(t4) do { \
    t4.x = wmma::__float_to_tf32(t4.x); t4.y = wmma::__float_to_tf32(t4.y); \
    t4.z = wmma::__float_to_tf32(t4.z); t4.w = wmma::__float_to_tf32(t4.w); } while(0)

// ============================================================
// Shared GEMM mainloop: C(128x128) = X @ W^T (K=768), tf32.
// Single-buffered smem, 8 warps with 64x32 tiles (acc 4x2).
// ============================================================
__device__ __forceinline__ void gemm_mainloop(const float* __restrict__ X,
                                              const float* __restrict__ W,
                                              float* As, float* Bs,
                                              int m0, int n0, int tid,
                                              int wm, int wn, FragC acc[4][2]) {
    const int r = tid >> 1;
    const int c0 = (tid & 1) * 16;
    const float* xp = X + (size_t)(m0 + r) * HH + c0;
    const float* wp = W + (size_t)(n0 + r) * HH + c0;

    for (int s = 0; s < NSLAB; s++) {
        #pragma unroll
        for (int i = 0; i < 4; i++) {
            float4 t4 = *(const float4*)(xp + s * SLABK + i * 4);
            CVT4(t4); *(float4*)&As[r * LDS + c0 + i * 4] = t4;
            float4 u4 = *(const float4*)(wp + s * SLABK + i * 4);
            CVT4(u4); *(float4*)&Bs[r * LDS + c0 + i * 4] = u4;
        }
        __syncthreads();
        #pragma unroll
        for (int kk = 0; kk < 4; kk++) {
            FragA a[4]; FragBc b[2];
            #pragma unroll
            for (int i = 0; i < 4; i++) wmma::load_matrix_sync(a[i], &As[(wm + i * 16) * LDS + kk * 8], LDS);
            #pragma unroll
            for (int j = 0; j < 2; j++) wmma::load_matrix_sync(b[j], &Bs[(wn + j * 16) * LDS + kk * 8], LDS);
            #pragma unroll
            for (int i = 0; i < 4; i++)
                #pragma unroll
                for (int j = 0; j < 2; j++) wmma::mma_sync(acc[i][j], a[i], b[j], acc[i][j]);
        }
        __syncthreads();
    }
}

// ============================================================
// Kernel 1: fused QKV projections, head-split output.
// ============================================================
__global__ void __launch_bounds__(256, 2)
proj_qkv_kernel(const float* __restrict__ q,
                const float* __restrict__ k,
                const float* __restrict__ v,
                const float* __restrict__ Wq, const float* __restrict__ bq,
                const float* __restrict__ Wk, const float* __restrict__ bk,
                const float* __restrict__ Wv, const float* __restrict__ bv) {
    const float* X; const float* W; const float* bias; float* Y;
    if (blockIdx.z == 0)      { X = q; W = Wq; bias = bq; Y = g_qh; }
    else if (blockIdx.z == 1) { X = k; W = Wk; bias = bk; Y = g_kh; }
    else                      { X = v; W = Wv; bias = bv; Y = g_vh; }

    extern __shared__ float sm[];
    float* As = sm;
    float* Bs = sm + 128 * LDS;
    float* Cs = sm;                    // reused post-mainloop (needs 128*LDQ)
    __shared__ float bias_s[128];

    const int tid = threadIdx.x;
    const int w = tid >> 5;
    const int m0 = blockIdx.y * 128, n0 = blockIdx.x * 128;
    const int wm = (w & 1) * 64, wn = (w >> 1) * 32;
    if (tid < 128) bias_s[tid] = bias[n0 + tid];

    FragC acc[4][2];
    #pragma unroll
    for (int i = 0; i < 4; i++)
        #pragma unroll
        for (int j = 0; j < 2; j++) wmma::fill_fragment(acc[i][j], 0.0f);

    gemm_mainloop(X, W, As, Bs, m0, n0, tid, wm, wn, acc);

    #pragma unroll
    for (int i = 0; i < 4; i++)
        #pragma unroll
        for (int j = 0; j < 2; j++)
            wmma::store_matrix_sync(&Cs[(wm + i * 16) * LDQ + wn + j * 16], acc[i][j], LDQ, wmma::mem_row_major);
    __syncthreads();

    {
        const int r = tid >> 1;
        const int c0 = (tid & 1) * 64;
        const int h = (n0 + c0) >> 6;
        const int m = m0 + r, b = m >> 11, s = m & 2047;
        float* dst = &Y[(((size_t)b * NH + h) * SS + s) * DD];
        #pragma unroll
        for (int t = 0; t < 16; t++) {
            float4 t4 = *(float4*)&Cs[r * LDQ + c0 + t * 4];
            t4.x += bias_s[c0 + t * 4];     t4.y += bias_s[c0 + t * 4 + 1];
            t4.z += bias_s[c0 + t * 4 + 2]; t4.w += bias_s[c0 + t * 4 + 3];
            *(float4*)&dst[t * 4] = t4;
        }
    }
}

// ============================================================
// Kernel 2: fused attention. No-max softmax, deferred norm with
// in-kernel renormalization of the attn rows (no rescale kernel).
// 256 threads, 128 Q rows per CTA, 64-col K/V chunks, 2 CTA/SM.
// ============================================================
__global__ void __launch_bounds__(256, 2)
fused_attn_kernel(const int* __restrict__ mask, float* __restrict__ attn) {
    extern __shared__ float sm[];
    float* Qs    = sm;                    // [128][LDP]
    float* Ks    = Qs + 128 * LDP;        // [64][LDP]
    float* Vs    = Ks + 64 * LDP;         // [64][LDP]
    float* ps    = Vs + 64 * LDP;         // [128][LDP]
    float* biasv = ps + 128 * LDP;        // [2048]

    const int tid = threadIdx.x;
    const int w = tid >> 5;
    const int bh = blockIdx.y;
    const int b = bh / NH, h = bh % NH;
    const int m0 = blockIdx.x * 128;
    const int wm = (w >> 1) * 32, wn = (w & 1) * 32;

    const float* qh_head = g_qh + (size_t)bh * SS * DD + (size_t)m0 * DD;
    const float* kh_head = g_kh + (size_t)bh * SS * DD;
    const float* vh_head = g_vh + (size_t)bh * SS * DD;

    // load Q tile (tf32) + mask bias
    #pragma unroll
    for (int jj = 0; jj < 2; jj++) {
        int e = tid + 256 * jj;
        int r = e >> 2, cc = (e & 3) * 16;
        #pragma unroll
        for (int i = 0; i < 4; i++) {
            float4 t4 = *(const float4*)&qh_head[(size_t)r * DD + cc + i * 4];
            CVT4(t4);
            *(float4*)&Qs[r * LDP + cc + i * 4] = t4;
        }
    }
    #pragma unroll
    for (int i = 0; i < 8; i++) {
        int c = tid + 256 * i;
        biasv[c] = mask[b * SS + c] ? NEGV : 0.0f;
    }
    __syncthreads();

    const int erow = tid >> 1, ec0 = (tid & 1) * 32;
    float l_run = 0.0f;

    FragC accv[2][2];
    #pragma unroll
    for (int i = 0; i < 2; i++)
        #pragma unroll
        for (int j = 0; j < 2; j++) wmma::fill_fragment(accv[i][j], 0.0f);

    float* arow = attn + ((size_t)bh * SS + m0 + erow) * SS;

    for (int c0 = 0; c0 < SS; c0 += 64) {
        // ---- load K + V chunk (tf32) ----
        {
            int kr = tid >> 2, cc = (tid & 3) * 16;
            const float* ksrc = kh_head + (size_t)(c0 + kr) * DD + cc;
            const float* vsrc = vh_head + (size_t)(c0 + kr) * DD + cc;
            #pragma unroll
            for (int i = 0; i < 4; i++) {
                float4 t4 = *(const float4*)(ksrc + i * 4);
                CVT4(t4); *(float4*)&Ks[kr * LDP + cc + i * 4] = t4;
                float4 u4 = *(const float4*)(vsrc + i * 4);
                CVT4(u4); *(float4*)&Vs[kr * LDP + cc + i * 4] = u4;
            }
        }
        __syncthreads();

        // ---- S = Q @ K^T for this chunk (128x64) ----
        {
            FragC sa[2][2];
            #pragma unroll
            for (int i = 0; i < 2; i++)
                #pragma unroll
                for (int j = 0; j < 2; j++) wmma::fill_fragment(sa[i][j], 0.0f);
            #pragma unroll
            for (int kk = 0; kk < 8; kk++) {
                FragA a0, a1; FragBc b0, b1;
                wmma::load_matrix_sync(a0, &Qs[(wm +  0) * LDP + kk * 8], LDP);
                wmma::load_matrix_sync(a1, &Qs[(wm + 16) * LDP + kk * 8], LDP);
                wmma::load_matrix_sync(b0, &Ks[(wn +  0) * LDP + kk * 8], LDP);
                wmma::load_matrix_sync(b1, &Ks[(wn + 16) * LDP + kk * 8], LDP);
                wmma::mma_sync(sa[0][0], a0, b0, sa[0][0]);
                wmma::mma_sync(sa[0][1], a0, b1, sa[0][1]);
                wmma::mma_sync(sa[1][0], a1, b0, sa[1][0]);
                wmma::mma_sync(sa[1][1], a1, b1, sa[1][1]);
            }
            #pragma unroll
            for (int i = 0; i < 2; i++)
                #pragma unroll
                for (int j = 0; j < 2; j++)
                    wmma::store_matrix_sync(&ps[(wm + i * 16) * LDP + wn + j * 16], sa[i][j], LDP, wmma::mem_row_major);
        }
        __syncthreads();

        // ---- p_u = exp(0.125*s + bias); write unnormalized attn ----
        {
            float lsum = 0.0f;
            #pragma unroll
            for (int i = 0; i < 8; i++) {
                int c = ec0 + i * 4;
                float4 t4 = *(float4*)&ps[erow * LDP + c];
                float4 b4 = *(const float4*)&biasv[c0 + c];
                float4 p4;
                p4.x = __expf(fmaf(t4.x, 0.125f, b4.x));
                p4.y = __expf(fmaf(t4.y, 0.125f, b4.y));
                p4.z = __expf(fmaf(t4.z, 0.125f, b4.z));
                p4.w = __expf(fmaf(t4.w, 0.125f, b4.w));
                lsum += p4.x + p4.y + p4.z + p4.w;
                *(float4*)&arow[c0 + c] = p4;
                CVT4(p4);
                *(float4*)&ps[erow * LDP + c] = p4;
            }
            l_run += lsum;
        }
        __syncthreads();

        // ---- AV accumulate: accv += P(128x64) @ V(64x64) ----
        #pragma unroll
        for (int kk = 0; kk < 8; kk++) {
            FragA a0, a1; FragBr b0, b1;
            wmma::load_matrix_sync(a0, &ps[(wm +  0) * LDP + kk * 8], LDP);
            wmma::load_matrix_sync(a1, &ps[(wm + 16) * LDP + kk * 8], LDP);
            wmma::load_matrix_sync(b0, &Vs[(kk * 8) * LDP + wn +  0], LDP);
            wmma::load_matrix_sync(b1, &Vs[(kk * 8) * LDP + wn + 16], LDP);
            wmma::mma_sync(accv[0][0], a0, b0, accv[0][0]);
            wmma::mma_sync(accv[0][1], a0, b1, accv[0][1]);
            wmma::mma_sync(accv[1][0], a1, b0, accv[1][0]);
            wmma::mma_sync(accv[1][1], a1, b1, accv[1][1]);
        }
        __syncthreads();
    }

    // row sum -> inverse (pair combine across the 2 threads of this row)
    l_run += __shfl_xor_sync(0xFFFFFFFFu, l_run, 1);
    const float inv_l = 1.0f / l_run;

    // ---- renormalize this thread's own attn slices in place ----
    #pragma unroll 4
    for (int c0 = 0; c0 < SS; c0 += 64) {
        #pragma unroll
        for (int i = 0; i < 8; i++) {
            float4 p4 = *(float4*)&arow[c0 + ec0 + i * 4];
            p4.x *= inv_l; p4.y *= inv_l; p4.z *= inv_l; p4.w *= inv_l;
            *(float4*)&arow[c0 + ec0 + i * 4] = p4;
        }
    }

    // ---- store AV accumulators, normalize, write ctx ----
    #pragma unroll
    for (int i = 0; i < 2; i++)
        #pragma unroll
        for (int j = 0; j < 2; j++)
            wmma::store_matrix_sync(&ps[(wm + i * 16) * LDP + wn + j * 16], accv[i][j], LDP, wmma::mem_row_major);
    __syncthreads();
    {
        float* dst = &g_ctx[((size_t)(b * SS + m0 + erow)) * HH + h * 64 + ec0];
        #pragma unroll
        for (int i = 0; i < 8; i++) {
            float4 t4 = *(float4*)&ps[erow * LDP + ec0 + i * 4];
            t4.x *= inv_l; t4.y *= inv_l; t4.z *= inv_l; t4.w *= inv_l;
            *(float4*)&dst[i * 4] = t4;
        }
    }
}

// ============================================================
// Kernel 3: out = ctx @ Wm^T + bm.
// ============================================================
__global__ void __launch_bounds__(256, 2)
out_proj_kernel(const float* __restrict__ Wm,
                const float* __restrict__ bm,
                float* __restrict__ out) {
    extern __shared__ float sm[];
    float* As = sm;
    float* Bs = sm + 128 * LDS;
    float* Cs = sm;
    __shared__ float bias_s[128];

    const int tid = threadIdx.x;
    const int w = tid >> 5;
    const int m0 = blockIdx.y * 128, n0 = blockIdx.x * 128;
    const int wm = (w & 1) * 64, wn = (w >> 1) * 32;
    if (tid < 128) bias_s[tid] = bm[n0 + tid];

    FragC acc[4][2];
    #pragma unroll
    for (int i = 0; i < 4; i++)
        #pragma unroll
        for (int j = 0; j < 2; j++) wmma::fill_fragment(acc[i][j], 0.0f);

    gemm_mainloop(g_ctx, Wm, As, Bs, m0, n0, tid, wm, wn, acc);

    #pragma unroll
    for (int i = 0; i < 4; i++)
        #pragma unroll
        for (int j = 0; j < 2; j++)
            wmma::store_matrix_sync(&Cs[(wm + i * 16) * LDQ + wn + j * 16], acc[i][j], LDQ, wmma::mem_row_major);
    __syncthreads();

    {
        const int r = tid >> 1;
        const int c0 = (tid & 1) * 64;
        float* dst = &out[(size_t)(m0 + r) * HH + n0 + c0];
        #pragma unroll
        for (int t = 0; t < 16; t++) {
            float4 t4 = *(float4*)&Cs[r * LDQ + c0 + t * 4];
            t4.x += bias_s[c0 + t * 4];     t4.y += bias_s[c0 + t * 4 + 1];
            t4.z += bias_s[c0 + t * 4 + 2]; t4.w += bias_s[c0 + t * 4 + 3];
            *(float4*)&dst[t * 4] = t4;
        }
    }
}

// ============================================================
// Host launcher
// ============================================================
extern "C" void kernel_launch(void* const* d_in, const int* in_sizes, int n_in,
                              void* d_out, int out_size) {
    const float* v    = (const float*)d_in[0];
    const float* k    = (const float*)d_in[1];
    const float* q    = (const float*)d_in[2];
    const int*   mask = (const int*)  d_in[3];
    const float* Wv   = (const float*)d_in[4];
    const float* bv   = (const float*)d_in[5];
    const float* Wk   = (const float*)d_in[6];
    const float* bk   = (const float*)d_in[7];
    const float* Wq   = (const float*)d_in[8];
    const float* bq   = (const float*)d_in[9];
    const float* Wm   = (const float*)d_in[10];
    const float* bm   = (const float*)d_in[11];
    float* out = (float*)d_out;

    float* attn;
    if ((size_t)out_size >= (size_t)OUT_ELEMS + ATTN_ELEMS) {
        attn = out + OUT_ELEMS;
    } else {
        void* p = nullptr;
        cudaGetSymbolAddress(&p, g_attn_scratch);
        attn = (float*)p;
    }

    const int SMEM_GEMM = 128 * LDQ * 4;                               // 67584 (covers As+Bs too)
    const int SMEM_FA   = (128 * LDP + 64 * LDP + 64 * LDP + 128 * LDP + 2048) * 4; // 112640
    static int smem_set = 0;
    if (!smem_set) {
        cudaFuncSetAttribute(proj_qkv_kernel, cudaFuncAttributeMaxDynamicSharedMemorySize, SMEM_GEMM);
        cudaFuncSetAttribute(out_proj_kernel, cudaFuncAttributeMaxDynamicSharedMemorySize, SMEM_GEMM);
        cudaFuncSetAttribute(fused_attn_kernel, cudaFuncAttributeMaxDynamicSharedMemorySize, SMEM_FA);
        smem_set = 1;
    }

    proj_qkv_kernel<<<dim3(HH / 128, M_PROJ / 128, 3), 256, SMEM_GEMM>>>(q, k, v, Wq, bq, Wk, bk, Wv, bv);
    fused_attn_kernel<<<dim3(SS / 128, BH), 256, SMEM_FA>>>(mask, attn);
    out_proj_kernel<<<dim3(HH / 128, M_PROJ / 128, 1), 256, SMEM_GEMM>>>(Wm, bm, out);
}

// round 7
// speedup vs baseline: 1.1523x; 1.1523x over previous
#include <cuda_runtime.h>
#include <mma.h>
using namespace nvcuda;

#define BB 2
#define SS 2048
#define HH 768
#define NH 12
#define DD 64
#define BH (BB*NH)
#define M_PROJ (BB*SS)
#define OUT_ELEMS (BB*SS*HH)
#define ATTN_ELEMS ((size_t)BB*NH*SS*SS)
#define NEGV (-1e32f)

__device__ float g_qh[BB*NH*SS*DD];
__device__ float g_kh[BB*NH*SS*DD];
__device__ float g_vh[BB*NH*SS*DD];
__device__ float g_ctx[BB*SS*HH];
__device__ float g_linv[BH*SS];
__device__ float g_attn_scratch[BB*NH*SS*SS];

typedef wmma::fragment<wmma::matrix_a, 16, 16, 8, wmma::precision::tf32, wmma::row_major> FragA;
typedef wmma::fragment<wmma::matrix_b, 16, 16, 8, wmma::precision::tf32, wmma::col_major> FragBc;
typedef wmma::fragment<wmma::matrix_b, 16, 16, 8, wmma::precision::tf32, wmma::row_major> FragBr;
typedef wmma::fragment<wmma::accumulator, 16, 16, 8, float> FragC;

#define LDS 36           // 32-k slab + 4 pad (proj kernel)
#define SLABK 32
#define NSLAB (HH/SLABK) // 24
#define LDP 68           // 64 + 4
#define LDQ 132          // 128 + 4
#define LDT 20           // 16-k slab + 4 pad (out_proj kernel)

#define CVT4(t4) do { \
    t4.x = wmma::__float_to_tf32(t4.x); t4.y = wmma::__float_to_tf32(t4.y); \
    t4.z = wmma::__float_to_tf32(t4.z); t4.w = wmma::__float_to_tf32(t4.w); } while(0)

// ============================================================
// Kernel 1: fused QKV projections (R6 config: 128x128 tile,
// 32-k slab single-buffered, 8 warps 64x32, grid 576).
// ============================================================
__global__ void __launch_bounds__(256, 2)
proj_qkv_kernel(const float* __restrict__ q,
                const float* __restrict__ k,
                const float* __restrict__ v,
                const float* __restrict__ Wq, const float* __restrict__ bq,
                const float* __restrict__ Wk, const float* __restrict__ bk,
                const float* __restrict__ Wv, const float* __restrict__ bv) {
    const float* X; const float* W; const float* bias; float* Y;
    if (blockIdx.z == 0)      { X = q; W = Wq; bias = bq; Y = g_qh; }
    else if (blockIdx.z == 1) { X = k; W = Wk; bias = bk; Y = g_kh; }
    else                      { X = v; W = Wv; bias = bv; Y = g_vh; }

    extern __shared__ float sm[];
    float* As = sm;
    float* Bs = sm + 128 * LDS;
    float* Cs = sm;
    __shared__ float bias_s[128];

    const int tid = threadIdx.x;
    const int w = tid >> 5;
    const int m0 = blockIdx.y * 128, n0 = blockIdx.x * 128;
    const int wm = (w & 1) * 64, wn = (w >> 1) * 32;
    if (tid < 128) bias_s[tid] = bias[n0 + tid];

    FragC acc[4][2];
    #pragma unroll
    for (int i = 0; i < 4; i++)
        #pragma unroll
        for (int j = 0; j < 2; j++) wmma::fill_fragment(acc[i][j], 0.0f);

    const int r = tid >> 1;
    const int c0 = (tid & 1) * 16;
    const float* xp = X + (size_t)(m0 + r) * HH + c0;
    const float* wp = W + (size_t)(n0 + r) * HH + c0;

    for (int s = 0; s < NSLAB; s++) {
        #pragma unroll
        for (int i = 0; i < 4; i++) {
            float4 t4 = *(const float4*)(xp + s * SLABK + i * 4);
            CVT4(t4); *(float4*)&As[r * LDS + c0 + i * 4] = t4;
            float4 u4 = *(const float4*)(wp + s * SLABK + i * 4);
            CVT4(u4); *(float4*)&Bs[r * LDS + c0 + i * 4] = u4;
        }
        __syncthreads();
        #pragma unroll
        for (int kk = 0; kk < 4; kk++) {
            FragA a[4]; FragBc b[2];
            #pragma unroll
            for (int i = 0; i < 4; i++) wmma::load_matrix_sync(a[i], &As[(wm + i * 16) * LDS + kk * 8], LDS);
            #pragma unroll
            for (int j = 0; j < 2; j++) wmma::load_matrix_sync(b[j], &Bs[(wn + j * 16) * LDS + kk * 8], LDS);
            #pragma unroll
            for (int i = 0; i < 4; i++)
                #pragma unroll
                for (int j = 0; j < 2; j++) wmma::mma_sync(acc[i][j], a[i], b[j], acc[i][j]);
        }
        __syncthreads();
    }

    #pragma unroll
    for (int i = 0; i < 4; i++)
        #pragma unroll
        for (int j = 0; j < 2; j++)
            wmma::store_matrix_sync(&Cs[(wm + i * 16) * LDQ + wn + j * 16], acc[i][j], LDQ, wmma::mem_row_major);
    __syncthreads();

    {
        const int rr = tid >> 1;
        const int cc = (tid & 1) * 64;
        const int h = (n0 + cc) >> 6;
        const int m = m0 + rr, b = m >> 11, s = m & 2047;
        float* dst = &Y[(((size_t)b * NH + h) * SS + s) * DD];
        #pragma unroll
        for (int t = 0; t < 16; t++) {
            float4 t4 = *(float4*)&Cs[rr * LDQ + cc + t * 4];
            t4.x += bias_s[cc + t * 4];     t4.y += bias_s[cc + t * 4 + 1];
            t4.z += bias_s[cc + t * 4 + 2]; t4.w += bias_s[cc + t * 4 + 3];
            *(float4*)&dst[t * 4] = t4;
        }
    }
}

// ============================================================
// Kernel 2: fused attention (R4 config). No-max softmax,
// unnormalized attn write, per-row 1/sum published to g_linv.
// 256 threads, 128 Q rows, 64-col K/V chunks, 2 CTA/SM.
// ============================================================
__global__ void __launch_bounds__(256, 2)
fused_attn_kernel(const int* __restrict__ mask, float* __restrict__ attn) {
    extern __shared__ float sm[];
    float* Qs    = sm;                    // [128][LDP]
    float* Ks    = Qs + 128 * LDP;        // [64][LDP]
    float* Vs    = Ks + 64 * LDP;         // [64][LDP]
    float* ps    = Vs + 64 * LDP;         // [128][LDP]
    float* biasv = ps + 128 * LDP;        // [2048]

    const int tid = threadIdx.x;
    const int w = tid >> 5;
    const int bh = blockIdx.y;
    const int b = bh / NH, h = bh % NH;
    const int m0 = blockIdx.x * 128;
    const int wm = (w >> 1) * 32, wn = (w & 1) * 32;

    const float* qh_head = g_qh + (size_t)bh * SS * DD + (size_t)m0 * DD;
    const float* kh_head = g_kh + (size_t)bh * SS * DD;
    const float* vh_head = g_vh + (size_t)bh * SS * DD;

    #pragma unroll
    for (int jj = 0; jj < 2; jj++) {
        int e = tid + 256 * jj;
        int r = e >> 2, cc = (e & 3) * 16;
        #pragma unroll
        for (int i = 0; i < 4; i++) {
            float4 t4 = *(const float4*)&qh_head[(size_t)r * DD + cc + i * 4];
            CVT4(t4);
            *(float4*)&Qs[r * LDP + cc + i * 4] = t4;
        }
    }
    #pragma unroll
    for (int i = 0; i < 8; i++) {
        int c = tid + 256 * i;
        biasv[c] = mask[b * SS + c] ? NEGV : 0.0f;
    }
    __syncthreads();

    const int erow = tid >> 1, ec0 = (tid & 1) * 32;
    float l_run = 0.0f;

    FragC accv[2][2];
    #pragma unroll
    for (int i = 0; i < 2; i++)
        #pragma unroll
        for (int j = 0; j < 2; j++) wmma::fill_fragment(accv[i][j], 0.0f);

    float* arow = attn + ((size_t)bh * SS + m0 + erow) * SS;

    for (int c0 = 0; c0 < SS; c0 += 64) {
        {
            int kr = tid >> 2, cc = (tid & 3) * 16;
            const float* ksrc = kh_head + (size_t)(c0 + kr) * DD + cc;
            const float* vsrc = vh_head + (size_t)(c0 + kr) * DD + cc;
            #pragma unroll
            for (int i = 0; i < 4; i++) {
                float4 t4 = *(const float4*)(ksrc + i * 4);
                CVT4(t4); *(float4*)&Ks[kr * LDP + cc + i * 4] = t4;
                float4 u4 = *(const float4*)(vsrc + i * 4);
                CVT4(u4); *(float4*)&Vs[kr * LDP + cc + i * 4] = u4;
            }
        }
        __syncthreads();

        {
            FragC sa[2][2];
            #pragma unroll
            for (int i = 0; i < 2; i++)
                #pragma unroll
                for (int j = 0; j < 2; j++) wmma::fill_fragment(sa[i][j], 0.0f);
            #pragma unroll
            for (int kk = 0; kk < 8; kk++) {
                FragA a0, a1; FragBc b0, b1;
                wmma::load_matrix_sync(a0, &Qs[(wm +  0) * LDP + kk * 8], LDP);
                wmma::load_matrix_sync(a1, &Qs[(wm + 16) * LDP + kk * 8], LDP);
                wmma::load_matrix_sync(b0, &Ks[(wn +  0) * LDP + kk * 8], LDP);
                wmma::load_matrix_sync(b1, &Ks[(wn + 16) * LDP + kk * 8], LDP);
                wmma::mma_sync(sa[0][0], a0, b0, sa[0][0]);
                wmma::mma_sync(sa[0][1], a0, b1, sa[0][1]);
                wmma::mma_sync(sa[1][0], a1, b0, sa[1][0]);
                wmma::mma_sync(sa[1][1], a1, b1, sa[1][1]);
            }
            #pragma unroll
            for (int i = 0; i < 2; i++)
                #pragma unroll
                for (int j = 0; j < 2; j++)
                    wmma::store_matrix_sync(&ps[(wm + i * 16) * LDP + wn + j * 16], sa[i][j], LDP, wmma::mem_row_major);
        }
        __syncthreads();

        {
            float lsum = 0.0f;
            #pragma unroll
            for (int i = 0; i < 8; i++) {
                int c = ec0 + i * 4;
                float4 t4 = *(float4*)&ps[erow * LDP + c];
                float4 b4 = *(const float4*)&biasv[c0 + c];
                float4 p4;
                p4.x = __expf(fmaf(t4.x, 0.125f, b4.x));
                p4.y = __expf(fmaf(t4.y, 0.125f, b4.y));
                p4.z = __expf(fmaf(t4.z, 0.125f, b4.z));
                p4.w = __expf(fmaf(t4.w, 0.125f, b4.w));
                lsum += p4.x + p4.y + p4.z + p4.w;
                *(float4*)&arow[c0 + c] = p4;
                CVT4(p4);
                *(float4*)&ps[erow * LDP + c] = p4;
            }
            l_run += lsum;
        }
        __syncthreads();

        #pragma unroll
        for (int kk = 0; kk < 8; kk++) {
            FragA a0, a1; FragBr b0, b1;
            wmma::load_matrix_sync(a0, &ps[(wm +  0) * LDP + kk * 8], LDP);
            wmma::load_matrix_sync(a1, &ps[(wm + 16) * LDP + kk * 8], LDP);
            wmma::load_matrix_sync(b0, &Vs[(kk * 8) * LDP + wn +  0], LDP);
            wmma::load_matrix_sync(b1, &Vs[(kk * 8) * LDP + wn + 16], LDP);
            wmma::mma_sync(accv[0][0], a0, b0, accv[0][0]);
            wmma::mma_sync(accv[0][1], a0, b1, accv[0][1]);
            wmma::mma_sync(accv[1][0], a1, b0, accv[1][0]);
            wmma::mma_sync(accv[1][1], a1, b1, accv[1][1]);
        }
        __syncthreads();
    }

    l_run += __shfl_xor_sync(0xFFFFFFFFu, l_run, 1);
    const float inv_l = 1.0f / l_run;
    if ((tid & 1) == 0) g_linv[bh * SS + m0 + erow] = inv_l;

    #pragma unroll
    for (int i = 0; i < 2; i++)
        #pragma unroll
        for (int j = 0; j < 2; j++)
            wmma::store_matrix_sync(&ps[(wm + i * 16) * LDP + wn + j * 16], accv[i][j], LDP, wmma::mem_row_major);
    __syncthreads();
    {
        float* dst = &g_ctx[((size_t)(b * SS + m0 + erow)) * HH + h * 64 + ec0];
        #pragma unroll
        for (int i = 0; i < 8; i++) {
            float4 t4 = *(float4*)&ps[erow * LDP + ec0 + i * 4];
            t4.x *= inv_l; t4.y *= inv_l; t4.z *= inv_l; t4.w *= inv_l;
            *(float4*)&dst[i * 4] = t4;
        }
    }
}

// ============================================================
// Kernel 3: attn rescale (block per row, coalesced streaming).
// ============================================================
__global__ void __launch_bounds__(256)
attn_scale_kernel(float* __restrict__ attn) {
    const int row = blockIdx.x;
    const float inv = g_linv[row];
    float* p = attn + (size_t)row * SS;
    const int t = threadIdx.x;
    #pragma unroll
    for (int i = 0; i < 2; i++) {
        int c = (t + i * 256) * 4;
        float4 v4 = *(float4*)&p[c];
        v4.x *= inv; v4.y *= inv; v4.z *= inv; v4.w *= inv;
        *(float4*)&p[c] = v4;
    }
}

// ============================================================
// Kernel 4: out = ctx @ Wm^T + bm (R3 config: 128x64 tile,
// 16-k slab, 8 warps 32x32, grid 384).
// ============================================================
__global__ void __launch_bounds__(256)
out_proj_kernel(const float* __restrict__ Wm,
                const float* __restrict__ bm,
                float* __restrict__ out) {
    __shared__ float sbuf[128 * LDP];
    __shared__ float bias_s[64];
    float* As = sbuf;                 // [128][LDT]
    float* Bs = sbuf + 128 * LDT;     // [64][LDT]
    float* Cs = sbuf;                 // [128][LDP]

    const int tid = threadIdx.x;
    const int w = tid >> 5;
    const int m0 = blockIdx.y * 128, n0 = blockIdx.x * 64;
    const int mw = (w >> 1) * 32, nw = (w & 1) * 32;
    if (tid < 64) bias_s[tid] = bm[n0 + tid];

    FragC acc[2][2];
    #pragma unroll
    for (int i = 0; i < 2; i++)
        #pragma unroll
        for (int j = 0; j < 2; j++) wmma::fill_fragment(acc[i][j], 0.0f);

    for (int k0 = 0; k0 < HH; k0 += 16) {
        #pragma unroll
        for (int jj = 0; jj < 2; jj++) {
            int e = tid + 256 * jj;
            int r = e >> 2, c4 = (e & 3) * 4;
            float4 t4 = *(const float4*)&g_ctx[(size_t)(m0 + r) * HH + k0 + c4];
            CVT4(t4);
            *(float4*)&As[r * LDT + c4] = t4;
        }
        {
            int r = tid >> 2, c4 = (tid & 3) * 4;
            float4 t4 = *(const float4*)&Wm[(size_t)(n0 + r) * HH + k0 + c4];
            CVT4(t4);
            *(float4*)&Bs[r * LDT + c4] = t4;
        }
        __syncthreads();
        #pragma unroll
        for (int kt = 0; kt < 2; kt++) {
            FragA a0, a1; FragBc b0, b1;
            wmma::load_matrix_sync(a0, &As[(mw +  0) * LDT + kt * 8], LDT);
            wmma::load_matrix_sync(a1, &As[(mw + 16) * LDT + kt * 8], LDT);
            wmma::load_matrix_sync(b0, &Bs[(nw +  0) * LDT + kt * 8], LDT);
            wmma::load_matrix_sync(b1, &Bs[(nw + 16) * LDT + kt * 8], LDT);
            wmma::mma_sync(acc[0][0], a0, b0, acc[0][0]);
            wmma::mma_sync(acc[0][1], a0, b1, acc[0][1]);
            wmma::mma_sync(acc[1][0], a1, b0, acc[1][0]);
            wmma::mma_sync(acc[1][1], a1, b1, acc[1][1]);
        }
        __syncthreads();
    }
    #pragma unroll
    for (int i = 0; i < 2; i++)
        #pragma unroll
        for (int j = 0; j < 2; j++)
            wmma::store_matrix_sync(&Cs[(mw + i * 16) * LDP + nw + j * 16], acc[i][j], LDP, wmma::mem_row_major);
    __syncthreads();

    #pragma unroll
    for (int jj = 0; jj < 8; jj++) {
        int e = tid + 256 * jj;
        int r = e >> 4, c4 = (e & 15) * 4;
        float4 t4 = *(float4*)&Cs[r * LDP + c4];
        t4.x += bias_s[c4]; t4.y += bias_s[c4 + 1];
        t4.z += bias_s[c4 + 2]; t4.w += bias_s[c4 + 3];
        *(float4*)&out[(size_t)(m0 + r) * HH + n0 + c4] = t4;
    }
}

// ============================================================
// Host launcher
// ============================================================
extern "C" void kernel_launch(void* const* d_in, const int* in_sizes, int n_in,
                              void* d_out, int out_size) {
    const float* v    = (const float*)d_in[0];
    const float* k    = (const float*)d_in[1];
    const float* q    = (const float*)d_in[2];
    const int*   mask = (const int*)  d_in[3];
    const float* Wv   = (const float*)d_in[4];
    const float* bv   = (const float*)d_in[5];
    const float* Wk   = (const float*)d_in[6];
    const float* bk   = (const float*)d_in[7];
    const float* Wq   = (const float*)d_in[8];
    const float* bq   = (const float*)d_in[9];
    const float* Wm   = (const float*)d_in[10];
    const float* bm   = (const float*)d_in[11];
    float* out = (float*)d_out;

    float* attn;
    if ((size_t)out_size >= (size_t)OUT_ELEMS + ATTN_ELEMS) {
        attn = out + OUT_ELEMS;
    } else {
        void* p = nullptr;
        cudaGetSymbolAddress(&p, g_attn_scratch);
        attn = (float*)p;
    }

    const int SMEM_GEMM = 128 * LDQ * 4;                                            // 67584
    const int SMEM_FA   = (128 * LDP + 64 * LDP + 64 * LDP + 128 * LDP + 2048) * 4; // 112640
    static int smem_set = 0;
    if (!smem_set) {
        cudaFuncSetAttribute(proj_qkv_kernel, cudaFuncAttributeMaxDynamicSharedMemorySize, SMEM_GEMM);
        cudaFuncSetAttribute(fused_attn_kernel, cudaFuncAttributeMaxDynamicSharedMemorySize, SMEM_FA);
        smem_set = 1;
    }

    proj_qkv_kernel<<<dim3(HH / 128, M_PROJ / 128, 3), 256, SMEM_GEMM>>>(q, k, v, Wq, bq, Wk, bk, Wv, bv);
    fused_attn_kernel<<<dim3(SS / 128, BH), 256, SMEM_FA>>>(mask, attn);
    attn_scale_kernel<<<BH * SS, 256>>>(attn);
    out_proj_kernel<<<dim3(HH / 64, M_PROJ / 128, 1), 256>>>(Wm, bm, out);
}